// round 6
// baseline (speedup 1.0000x reference)
#include <cuda_runtime.h>
#include <cuda_bf16.h>

// ---------------------------------------------------------------------------
// Problem constants (fixed by the dataset)
// ---------------------------------------------------------------------------
#define S_LEN   256
#define BSZ     64
#define IN_DIM  128
#define HID     128
#define NT      2
#define TAPELEN 128
#define DIM     64          // HID / NT
#define LH      64          // HID / 2
#define G4      256         // 4 * LH

#define N_ROWS  (S_LEN * BSZ)          // 16384

// d_out layout: outputs [S,B,HID], tape [TL,B,NT,DIM], rpos [TL,B,NT], wpos [TL,B,NT]
#define OUT_OUTPUTS_SZ  (S_LEN * BSZ * HID)                 // 2097152
#define OUT_TAPE_OFF    (OUT_OUTPUTS_SZ)
#define OUT_TAPE_SZ     (TAPELEN * BSZ * NT * DIM)          // 1048576
#define OUT_RPOS_OFF    (OUT_TAPE_OFF + OUT_TAPE_SZ)
#define OUT_POS_SZ      (TAPELEN * BSZ * NT)                // 16384
#define OUT_WPOS_OFF    (OUT_RPOS_OFF + OUT_POS_SZ)
#define OUT_TOTAL       (OUT_WPOS_OFF + OUT_POS_SZ)

typedef unsigned long long u64;

// ---------------------------------------------------------------------------
// f32x2 packed-math helpers (Blackwell FFMA2 path — PTX only)
// ---------------------------------------------------------------------------
__device__ __forceinline__ u64 pack2(float x, float y) {
    u64 r; asm("mov.b64 %0, {%1, %2};" : "=l"(r) : "f"(x), "f"(y)); return r;
}
__device__ __forceinline__ u64 dup2(float x) { return pack2(x, x); }
__device__ __forceinline__ void unpack2(u64 v, float& x, float& y) {
    asm("mov.b64 {%0, %1}, %2;" : "=f"(x), "=f"(y) : "l"(v));
}
__device__ __forceinline__ u64 ffma2(u64 a, u64 b, u64 c) {
    u64 d; asm("fma.rn.f32x2 %0, %1, %2, %3;" : "=l"(d) : "l"(a), "l"(b), "l"(c)); return d;
}
__device__ __forceinline__ u64 fadd2(u64 a, u64 b) {
    u64 d; asm("add.rn.f32x2 %0, %1, %2;" : "=l"(d) : "l"(a), "l"(b)); return d;
}
__device__ __forceinline__ u64 fmul2(u64 a, u64 b) {
    u64 d; asm("mul.rn.f32x2 %0, %1, %2;" : "=l"(d) : "l"(a), "l"(b)); return d;
}
__device__ __forceinline__ u64 shflx_u64(u64 v, int m) {
    float x, y; unpack2(v, x, y);
    x = __shfl_xor_sync(0xffffffffu, x, m);
    y = __shfl_xor_sync(0xffffffffu, y, m);
    return pack2(x, y);
}

__device__ __forceinline__ float sigmoidf_(float x) {
    return 1.0f / (1.0f + __expf(-x));
}
// tanh(x) = 2*sigmoid(2x) - 1  — MUFU-based, NaN-free at +/- inf
__device__ __forceinline__ float tanh_fast(float x) {
    return 2.0f / (1.0f + __expf(-2.0f * x)) - 1.0f;
}

// ---------------------------------------------------------------------------
// Scratch (device globals — no allocations allowed)
// ---------------------------------------------------------------------------
__device__ float g_xproj_f[N_ROWS * G4];     // 16.8 MB
__device__ float g_xproj_r[N_ROWS * G4];     // 16.8 MB
__device__ float g_values [N_ROWS * HID];    //  8.4 MB
__device__ float g_hidden [N_ROWS * HID];    //  8.4 MB
__device__ float g_params [N_ROWS * NT * 8]; //  1.0 MB
__device__ float g_readout[N_ROWS * HID];    //  8.4 MB

// ---------------------------------------------------------------------------
// GEMM core: C[M,N] = A[M,128] * B[N,128]^T + bias1[N] (+ bias2[N])
// BM=128, BN=64, BK=32, 256 threads, 8x4 microtile with row-paired f32x2 accs.
// ---------------------------------------------------------------------------
__device__ __forceinline__ void gemm_tile(
    const float* __restrict__ A, const float* __restrict__ B,
    const float* __restrict__ b1, const float* __restrict__ b2,
    float* __restrict__ C, int N, int row0, int col0)
{
    __shared__ __align__(16) float As[32][130];
    __shared__ __align__(16) float Bs[32][65];

    int tid = threadIdx.x;
    int tx = tid & 15;          // col group (4 cols)
    int ty = tid >> 4;          // row group (8 rows)

    const float4* A4 = (const float4*)A;
    const float4* B4 = (const float4*)B;

    u64 acc[4][4];
#pragma unroll
    for (int i = 0; i < 4; i++)
#pragma unroll
        for (int j = 0; j < 4; j++) acc[i][j] = 0ull;

#pragma unroll
    for (int kt = 0; kt < 4; kt++) {
#pragma unroll
        for (int rep = 0; rep < 4; rep++) {
            int e = tid + 256 * rep;
            int r = e >> 3, k4 = e & 7;
            float4 v = A4[(size_t)(row0 + r) * 32 + kt * 8 + k4];
            As[k4 * 4 + 0][r] = v.x; As[k4 * 4 + 1][r] = v.y;
            As[k4 * 4 + 2][r] = v.z; As[k4 * 4 + 3][r] = v.w;
        }
#pragma unroll
        for (int rep = 0; rep < 2; rep++) {
            int e = tid + 256 * rep;
            int r = e >> 3, k4 = e & 7;
            float4 v = B4[(size_t)(col0 + r) * 32 + kt * 8 + k4];
            Bs[k4 * 4 + 0][r] = v.x; Bs[k4 * 4 + 1][r] = v.y;
            Bs[k4 * 4 + 2][r] = v.z; Bs[k4 * 4 + 3][r] = v.w;
        }
        __syncthreads();

#pragma unroll
        for (int kk = 0; kk < 32; kk++) {
            u64 a2[4];
#pragma unroll
            for (int ip = 0; ip < 4; ip++)
                a2[ip] = *(const u64*)&As[kk][ty * 8 + 2 * ip];
#pragma unroll
            for (int j = 0; j < 4; j++) {
                u64 bd = dup2(Bs[kk][tx * 4 + j]);
#pragma unroll
                for (int ip = 0; ip < 4; ip++)
                    acc[ip][j] = ffma2(a2[ip], bd, acc[ip][j]);
            }
        }
        __syncthreads();
    }

#pragma unroll
    for (int j = 0; j < 4; j++) {
        int col = col0 + tx * 4 + j;
        float bv = b1[col] + (b2 ? b2[col] : 0.0f);
#pragma unroll
        for (int ip = 0; ip < 4; ip++) {
            float x, y; unpack2(acc[ip][j], x, y);
            int row = row0 + ty * 8 + 2 * ip;
            C[(size_t)row * N + col]       = x + bv;
            C[(size_t)(row + 1) * N + col] = y + bv;
        }
    }
}

// Fused input projections: 3 GEMMs (f-gates 256 cols, r-gates 256 cols, values 128 cols)
__global__ __launch_bounds__(256) void gemm_fused_in(
    const float* __restrict__ A,
    const float* __restrict__ Wf, const float* __restrict__ bf1, const float* __restrict__ bf2,
    const float* __restrict__ Wr, const float* __restrict__ br1, const float* __restrict__ br2,
    const float* __restrict__ Wv, const float* __restrict__ bv1,
    float* __restrict__ Cf, float* __restrict__ Cr, float* __restrict__ Cv)
{
    int cb = blockIdx.x;            // 0..9
    int row0 = blockIdx.y * 128;
    if (cb < 4)      gemm_tile(A, Wf, bf1, bf2,     Cf, G4,  row0, cb * 64);
    else if (cb < 8) gemm_tile(A, Wr, br1, br2,     Cr, G4,  row0, (cb - 4) * 64);
    else             gemm_tile(A, Wv, bv1, nullptr, Cv, HID, row0, (cb - 8) * 64);
}

__global__ __launch_bounds__(256) void gemm_k128(
    const float* __restrict__ A, const float* __restrict__ B,
    const float* __restrict__ b1, float* __restrict__ C, int N)
{
    gemm_tile(A, B, b1, nullptr, C, N, blockIdx.y * 128, blockIdx.x * 64);
}

// ---------------------------------------------------------------------------
// Kernel 2: bidirectional LSTM recurrence. One block per (batch, direction).
// Thread j owns gate j (W_hh row j resident in 32 f32x2 registers).
// xp pre-activation for step s+1 is prefetched during step s.
// ---------------------------------------------------------------------------
__global__ __launch_bounds__(256) void lstm_k(
    const float* __restrict__ xpf, const float* __restrict__ xpr,
    const float* __restrict__ Whh_f, const float* __restrict__ Whh_r,
    float* __restrict__ hidden)
{
    int b   = blockIdx.x & 63;
    int dir = blockIdx.x >> 6;
    int j   = threadIdx.x;

    const float* Whh = dir ? Whh_r : Whh_f;
    const float* xp  = dir ? xpr   : xpf;

    u64 w2[32];
    const u64* wrow = (const u64*)(Whh + j * 64);
#pragma unroll
    for (int k = 0; k < 32; k++) w2[k] = wrow[k];

    __shared__ __align__(16) float h_sm[64];
    __shared__ float act[256];
    if (j < 64) h_sm[j] = 0.0f;
    float c = 0.0f;
    __syncthreads();

    const u64* h2 = (const u64*)h_sm;
    const float* xbase = xp + (size_t)b * G4 + j;

    int s   = dir ? (S_LEN - 1) : 0;
    int stp = dir ? -1 : 1;
    float gn = __ldg(&xbase[(size_t)s * (BSZ * G4)]);   // prefetch step 0

    for (int ss = 0; ss < S_LEN; ss++) {
        float g = gn;
        int s_cur = s;
        s += stp;
        if (ss + 1 < S_LEN)
            gn = __ldg(&xbase[(size_t)s * (BSZ * G4)]);  // prefetch next step

        u64 a0 = 0ull, a1 = 0ull, a2 = 0ull, a3 = 0ull;
#pragma unroll
        for (int k = 0; k < 32; k += 4) {
            a0 = ffma2(w2[k + 0], h2[k + 0], a0);
            a1 = ffma2(w2[k + 1], h2[k + 1], a1);
            a2 = ffma2(w2[k + 2], h2[k + 2], a2);
            a3 = ffma2(w2[k + 3], h2[k + 3], a3);
        }
        u64 at = fadd2(fadd2(a0, a1), fadd2(a2, a3));
        float sx, sy; unpack2(at, sx, sy);
        g += sx + sy;

        float av = (j >= 128 && j < 192) ? tanh_fast(g) : sigmoidf_(g);
        act[j] = av;
        __syncthreads();

        if (j < 64) {
            c = act[64 + j] * c + act[j] * act[128 + j];
            float h = act[192 + j] * tanh_fast(c);
            h_sm[j] = h;
            hidden[(size_t)(s_cur * BSZ + b) * HID + dir * 64 + j] = h;
        }
        __syncthreads();
    }
}

// ---------------------------------------------------------------------------
// Kernel 3: action head + nonlinearities. One thread per (row, tape).
// params[row][t][8] = {rd0,rd1,rd2, wd0,wd1,wd2, rw_read, rw_write}
// ---------------------------------------------------------------------------
__global__ __launch_bounds__(256) void act_k(
    const float* __restrict__ hidden, const float* __restrict__ Wact,
    const float* __restrict__ bact, float* __restrict__ params)
{
    int gt  = blockIdx.x * 256 + threadIdx.x;   // 0 .. 32767
    int row = gt >> 1;
    int t   = gt & 1;

    const float4* h4 = (const float4*)(hidden + (size_t)row * HID);
    const float4* w4 = (const float4*)Wact;

    float acc[8];
#pragma unroll
    for (int jj = 0; jj < 8; jj++) acc[jj] = 0.0f;

#pragma unroll 4
    for (int k4 = 0; k4 < 32; k4++) {
        float4 h = __ldg(&h4[k4]);
#pragma unroll
        for (int jj = 0; jj < 8; jj++) {
            float4 w = __ldg(&w4[(t * 8 + jj) * 32 + k4]);
            acc[jj] += h.x * w.x + h.y * w.y + h.z * w.z + h.w * w.w;
        }
    }
#pragma unroll
    for (int jj = 0; jj < 8; jj++) acc[jj] += bact[t * 8 + jj];

    float out[8];
    float m = fmaxf(acc[0], fmaxf(acc[1], acc[2]));
    float e0 = __expf(acc[0] - m), e1 = __expf(acc[1] - m), e2 = __expf(acc[2] - m);
    float inv = 1.0f / (e0 + e1 + e2);
    out[0] = e0 * inv; out[1] = e1 * inv; out[2] = e2 * inv;
    m = fmaxf(acc[3], fmaxf(acc[4], acc[5]));
    e0 = __expf(acc[3] - m); e1 = __expf(acc[4] - m); e2 = __expf(acc[5] - m);
    inv = 1.0f / (e0 + e1 + e2);
    out[3] = e0 * inv; out[4] = e1 * inv; out[5] = e2 * inv;
    out[6] = sigmoidf_(acc[6]);
    out[7] = sigmoidf_(acc[7]);

    float4* p4 = (float4*)(params + (size_t)gt * 8);
    p4[0] = make_float4(out[0], out[1], out[2], out[3]);
    p4[1] = make_float4(out[4], out[5], out[6], out[7]);
}

// ---------------------------------------------------------------------------
// Kernel 4: tape scan — WARP-AUTONOMOUS, fine split. 2048 one-warp blocks,
// zero barriers, zero smem. Block = (b, t, cpgroup g in [0,16)).
// Warp = 2 lane-groups of 16; group cg = lane>>4 owns column pair
// cp = 2g + cg across all 128 levels; lane r = lane&15 owns levels 8r..8r+7:
//   tape        : 8 u64 registers (f32x2 column pair per level)
//   wpos/rpos   : 8 u64 registers each, PACKED DUP'D (p,p) — dot loop and
//                 position update run entirely on FFMA2 with zero pack movs.
// Per step: dual dot + sw (3 FFMA2/level) -> 4-round shfl_xor butterfly over
// the 16-lane group -> delta/readout -> tape update -> position update
// (ring neighbors via 2 scalar shuffles + re-dup).
// ---------------------------------------------------------------------------
__global__ __launch_bounds__(32) void tape_k(
    const float* __restrict__ values, const float* __restrict__ params,
    float* __restrict__ readouts,
    float* __restrict__ out_tape, float* __restrict__ out_rpos,
    float* __restrict__ out_wpos)
{
    int bx = blockIdx.x;            // ((b*2 + t)*16 + g)
    int g  = bx & 15;
    int t  = (bx >> 4) & 1;
    int b  = bx >> 5;

    int lane = threadIdx.x;
    int cg   = lane >> 4;           // group within warp (0..1)
    int r    = lane & 15;           // lane-row within group
    int cp   = 2 * g + cg;          // column pair owned (0..31)
    int l0   = r * 8;               // first level owned

    // shuffle source lanes for ring neighbors (within the 16-lane group)
    int src_up = (lane & 16) | ((r + 1) & 15);   // holds level (l0+8) % 128
    int src_dn = (lane & 16) | ((r - 1) & 15);   // holds level (l0-1) & 127

    u64 tp[8], wp2[8], rp2[8];
#pragma unroll
    for (int i = 0; i < 8; i++) {
        tp[i] = 0ull;
        u64 v = (r == 0 && i == 0) ? dup2(1.0f) : 0ull;
        wp2[i] = v; rp2[i] = v;
    }

    // prefetch step 0
    const float* vbase = values + (size_t)b * HID + t * 64 + 2 * cp;
    const float4* pbase = (const float4*)(params + ((size_t)b * 2 + t) * 8);
    u64 val2 = __ldg((const u64*)vbase);
    float4 pp0 = __ldg(&pbase[0]);
    float4 pp1 = __ldg(&pbase[1]);

    for (int s = 0; s < S_LEN; s++) {
        int sb = s * BSZ + b;

        // --- dual dot products + sw (fully packed, 3 FFMA2/level) ---
        u64 owp = 0ull, orp = 0ull, sw2 = 0ull;
#pragma unroll
        for (int i = 0; i < 8; i++) {
            owp = ffma2(tp[i],  wp2[i], owp);
            orp = ffma2(tp[i],  rp2[i], orp);
            sw2 = ffma2(wp2[i], rp2[i], sw2);
        }
        // --- butterfly reduce over the 16-lane group (4 rounds) ---
#pragma unroll
        for (int m = 1; m <= 8; m <<= 1) {
            owp = fadd2(owp, shflx_u64(owp, m));
            orp = fadd2(orp, shflx_u64(orp, m));
            sw2 = fadd2(sw2, shflx_u64(sw2, m));
        }

        // --- delta, readout ---
        u64 d2  = fmul2(ffma2(owp, dup2(-1.0f), val2), dup2(pp1.w));
        u64 ro2 = fmul2(ffma2(d2, sw2, orp), dup2(pp1.z));
        if (r == 0) {
            float rox, roy; unpack2(ro2, rox, roy);
            *(float2*)(readouts + (size_t)sb * HID + t * 64 + 2 * cp) =
                make_float2(rox, roy);
        }

        // --- prefetch next step (overlaps with update math) ---
        float4 np0 = pp0, np1 = pp1;
        u64 nval = val2;
        if (s + 1 < S_LEN) {
            int sn = (s + 1) * BSZ + b;
            nval = __ldg((const u64*)(values + (size_t)sn * HID + t * 64 + 2 * cp));
            const float4* pb = (const float4*)(params + ((size_t)sn * 2 + t) * 8);
            np0 = __ldg(&pb[0]);
            np1 = __ldg(&pb[1]);
        }

        // --- tape update (register rank-1, uses OLD wp2) ---
#pragma unroll
        for (int i = 0; i < 8; i++)
            tp[i] = ffma2(wp2[i], d2, tp[i]);

        // --- position update (packed; ring neighbors via 2 scalar shuffles) ---
        float rt_s, rb_s, dmy;
        unpack2(rp2[0], rt_s, dmy);
        unpack2(rp2[7], rb_s, dmy);
        rt_s = __shfl_sync(0xffffffffu, rt_s, src_up);  // rpos[(l0+8)%128]
        rb_s = __shfl_sync(0xffffffffu, rb_s, src_dn);  // rpos[(l0-1)&127]
        u64 rtop2 = dup2(rt_s);
        u64 rbot2 = dup2(rb_s);

        u64 rd0_2 = dup2(pp0.x), rd1_2 = dup2(pp0.y), rd2_2 = dup2(pp0.z);
        u64 wd0_2 = dup2(pp0.w), wd1_2 = dup2(pp1.x), wd2_2 = dup2(pp1.y);

        u64 prev2 = rbot2;
#pragma unroll
        for (int i = 0; i < 8; i++) {
            u64 curr2 = rp2[i];
            u64 next2 = (i < 7) ? rp2[i + 1] : rtop2;
            // wpos'[l] = rpos[l+1]*wd0 + wpos[l]*wd1 + rpos[l-1]*wd2
            wp2[i] = ffma2(next2, wd0_2, ffma2(wp2[i], wd1_2, fmul2(prev2, wd2_2)));
            // rpos'[l] = rpos[l+1]*rd0 + rpos[l]*rd1 + rpos[l-1]*rd2
            rp2[i] = ffma2(next2, rd0_2, ffma2(curr2,  rd1_2, fmul2(prev2, rd2_2)));
            prev2 = curr2;
        }

        val2 = nval; pp0 = np0; pp1 = np1;
    }

    // --- final state -> d_out ---
    if (out_tape) {
#pragma unroll
        for (int i = 0; i < 8; i++) {
            int l = l0 + i;
            float x, y; unpack2(tp[i], x, y);
            *(float2*)(out_tape + ((size_t)(l * BSZ + b) * 2 + t) * 64 + 2 * cp) =
                make_float2(x, y);
        }
        if (cg == 0) {      // one group writes the (replicated) positions
#pragma unroll
            for (int i = 0; i < 8; i++) {
                int l = l0 + i;
                float rx, wx, d_;
                unpack2(rp2[i], rx, d_);
                unpack2(wp2[i], wx, d_);
                out_rpos[(size_t)(l * BSZ + b) * 2 + t] = rx;
                out_wpos[(size_t)(l * BSZ + b) * 2 + t] = wx;
            }
        }
    }
}

// ---------------------------------------------------------------------------
// Launcher
// ---------------------------------------------------------------------------
extern "C" void kernel_launch(void* const* d_in, const int* in_sizes, int n_in,
                              void* d_out, int out_size)
{
    const float* inputs = (const float*)d_in[0];
    const float* W_ih_f = (const float*)d_in[2];
    const float* W_hh_f = (const float*)d_in[3];
    const float* b_ih_f = (const float*)d_in[4];
    const float* b_hh_f = (const float*)d_in[5];
    const float* W_ih_r = (const float*)d_in[6];
    const float* W_hh_r = (const float*)d_in[7];
    const float* b_ih_r = (const float*)d_in[8];
    const float* b_hh_r = (const float*)d_in[9];
    const float* W_act  = (const float*)d_in[10];
    const float* b_act  = (const float*)d_in[11];
    const float* W_val  = (const float*)d_in[12];
    const float* b_val  = (const float*)d_in[13];
    const float* W_out  = (const float*)d_in[14];
    const float* b_out  = (const float*)d_in[15];

    float* out = (float*)d_out;

    float *xf, *xr, *vals, *hid, *prm, *ro;
    cudaGetSymbolAddress((void**)&xf,   g_xproj_f);
    cudaGetSymbolAddress((void**)&xr,   g_xproj_r);
    cudaGetSymbolAddress((void**)&vals, g_values);
    cudaGetSymbolAddress((void**)&hid,  g_hidden);
    cudaGetSymbolAddress((void**)&prm,  g_params);
    cudaGetSymbolAddress((void**)&ro,   g_readout);

    // Phase 1: fused input projections (one launch, 1280 blocks)
    gemm_fused_in<<<dim3(10, N_ROWS / 128), 256>>>(
        inputs,
        W_ih_f, b_ih_f, b_hh_f,
        W_ih_r, b_ih_r, b_hh_r,
        W_val,  b_val,
        xf, xr, vals);

    // Phase 2: LSTM recurrence (128 blocks: batch x direction)
    lstm_k<<<128, 256>>>(xf, xr, W_hh_f, W_hh_r, hid);

    // Phase 3: action head
    act_k<<<128, 256>>>(hid, W_act, b_act, prm);

    // Phase 4: tape scan (2048 one-warp blocks: batch x tape x cpgroup)
    bool full_out = (out_size >= OUT_TOTAL);
    tape_k<<<2048, 32>>>(vals, prm, ro,
                         full_out ? out + OUT_TAPE_OFF : nullptr,
                         full_out ? out + OUT_RPOS_OFF : nullptr,
                         full_out ? out + OUT_WPOS_OFF : nullptr);

    // Phase 5: output projection straight into d_out
    gemm_k128<<<dim3(HID / 64, N_ROWS / 128), 256>>>(ro, W_out, b_out, out, HID);
}